// round 12
// baseline (speedup 1.0000x reference)
#include <cuda_runtime.h>
#include <cuda_bf16.h>
#include <cstdint>

#define NUM_USERS 200000
#define NUM_ITEMS 100000
#define NUM_NODES (NUM_USERS + NUM_ITEMS)
#define NUM_EDGES 600000
#define DIM 128
#define BATCH 16384
#define BPB 128
#define S 132   // smem row stride (floats): conflict-free fragment access

// ---------------- scratch (static device globals) ---------------------------
// INVARIANT: g_mask is all-zero at entry to every kernel_launch call.
// (Zero-initialized at load; k_pairs clears every bit it set, every call.)
__device__ __align__(16) float g_agg[(size_t)NUM_NODES * DIM];
__device__ __align__(16) unsigned char g_mask[NUM_NODES];
__device__ __align__(16) float g_M[DIM * DIM];      // W^T W, tf32-rounded (symmetric)
__device__ __align__(16) float g_v[DIM];            // W^T b (fp32)
__device__ float g_c;                               // b.b

__device__ __forceinline__ float tf32r(float x) {
    unsigned u = __float_as_uint(x);
    u = (u + 0x1000u) & 0xFFFFE000u;
    return __uint_as_float(u);
}

// ---------------- K_m (side stream): M = W^T W (tf32), v = W^T b, c = b.b ----
__global__ void k_m(const float* __restrict__ W, const float* __restrict__ b) {
    int r = blockIdx.x;      // 0..127
    int c = threadIdx.x;     // 0..127
    float a0 = 0.f, a1 = 0.f, a2 = 0.f, a3 = 0.f;
#pragma unroll
    for (int j = 0; j < DIM; j += 4) {
        a0 += __ldg(&W[(j + 0) * DIM + r]) * __ldg(&W[(j + 0) * DIM + c]);
        a1 += __ldg(&W[(j + 1) * DIM + r]) * __ldg(&W[(j + 1) * DIM + c]);
        a2 += __ldg(&W[(j + 2) * DIM + r]) * __ldg(&W[(j + 2) * DIM + c]);
        a3 += __ldg(&W[(j + 3) * DIM + r]) * __ldg(&W[(j + 3) * DIM + c]);
    }
    g_M[r * DIM + c] = tf32r((a0 + a1) + (a2 + a3));
    if (r == 0) {
        float vv = 0.f;
#pragma unroll 8
        for (int j = 0; j < DIM; j++) vv += __ldg(&b[j]) * __ldg(&W[j * DIM + c]);
        g_v[c] = vv;
        if (c == 0) {
            float s = 0.f;
#pragma unroll 8
            for (int j = 0; j < DIM; j++) s += b[j] * b[j];
            g_c = s;
        }
    }
}

// ---------------- K_mark (main stream): mark needed nodes + zero agg rows ----
// 1024 blocks x 256 threads; 8 warps x 4 rows, indices prefetched (MLP 4).
#define MARKBLOCKS (2 * BATCH / 32)
__global__ void k_mark(const int* __restrict__ ui, const int* __restrict__ ii) {
    int warp = threadIdx.x >> 5, lane = threadIdx.x & 31;
    int rowbase = blockIdx.x * 32 + warp * 4;
    int nodes[4];
#pragma unroll
    for (int q = 0; q < 4; q++) {
        int ref = rowbase + q;
        nodes[q] = (ref < BATCH) ? __ldg(&ui[ref])
                                 : (NUM_USERS + __ldg(&ii[ref - BATCH]));
    }
    const float4 z = make_float4(0.f, 0.f, 0.f, 0.f);
#pragma unroll
    for (int q = 0; q < 4; q++)
        ((float4*)(g_agg + (size_t)nodes[q] * DIM))[lane] = z;
    if (lane == 0) {
#pragma unroll
        for (int q = 0; q < 4; q++) g_mask[nodes[q]] = 1;
    }
}

// ---------------- K1: scan edges, gather + vectorized scatter-add ------------
__global__ void k_edge(const int* __restrict__ src, const int* __restrict__ dst,
                       const float* __restrict__ uemb, const float* __restrict__ iemb) {
    int e = blockIdx.x * blockDim.x + threadIdx.x;
    int lane = threadIdx.x & 31;
    bool pass = false;
    int d = 0, s = 0;
    if (e < NUM_EDGES) {
        d = dst[e];
        pass = (g_mask[d] != 0);
        if (pass) s = src[e];
    }
    unsigned m = __ballot_sync(0xffffffffu, pass);
    while (m) {
        int bit = __ffs(m) - 1;
        m &= m - 1;
        int ds = __shfl_sync(0xffffffffu, d, bit);
        int ss = __shfl_sync(0xffffffffu, s, bit);
        const float* sp = (ss < NUM_USERS)
                            ? (uemb + (size_t)ss * DIM)
                            : (iemb + (size_t)(ss - NUM_USERS) * DIM);
        float4 v = ((const float4*)sp)[lane];
        float* a = g_agg + (size_t)ds * DIM + lane * 4;
        asm volatile("red.global.add.v4.f32 [%0], {%1, %2, %3, %4};"
                     :: "l"(a), "f"(v.x), "f"(v.y), "f"(v.z), "f"(v.w)
                     : "memory");
    }
}

// ---------------- K2: mma.sync tf32 GEMM + fused bilinear epilogue -----------
// Per block (128 pairs): Y[128,128] = XI @ M (tf32 HMMA), then
// out_i = sum_j [ xu_ij*(Y_ij + v_j) + v_j*xi_ij ] + b.b
// Also clears g_mask for its 256 nodes (restores the all-zero invariant).
#define MS_OFF   0
#define XI_OFF   (DIM * S * 4)
#define XU_OFF   (2 * DIM * S * 4)
#define VV_OFF   (3 * DIM * S * 4)
#define NDI_OFF  (VV_OFF + 512)
#define NDU_OFF  (NDI_OFF + 512)
#define PART_OFF (NDU_OFF + 512)
#define SMEM_K3  (PART_OFF + 2048)

__global__ void __launch_bounds__(512) k_pairs(
    const int* __restrict__ ui, const int* __restrict__ ii,
    float* __restrict__ out)
{
    extern __shared__ char sm[];
    float* Msm  = (float*)(sm + MS_OFF);    // Msm[j][k] (symmetric M)
    float* XIs  = (float*)(sm + XI_OFF);    // XIs[i][k], tf32-rounded
    float* XUs  = (float*)(sm + XU_OFF);    // XUs[i][k], fp32
    float* Vv   = (float*)(sm + VV_OFF);
    int*   Ndi  = (int*)(sm + NDI_OFF);
    int*   Ndu  = (int*)(sm + NDU_OFF);
    float* Part = (float*)(sm + PART_OFF);  // [128][4]

    int tid = threadIdx.x, warp = tid >> 5, lane = tid & 31;
    int base = blockIdx.x * BPB;
    int g = lane >> 2, t = lane & 3;

    // stage node indices + v
    if (tid < 128) {
        Ndi[tid] = NUM_USERS + __ldg(&ii[base + tid]);
        Ndu[tid] = __ldg(&ui[base + tid]);
        Vv[tid]  = g_v[tid];
    }
    // stage M with restride; float4, conflict-free
    for (int idx = tid; idx < DIM * DIM / 4; idx += 512) {
        int r = idx >> 5, c4 = idx & 31;
        *(float4*)&Msm[r * S + 4 * c4] = ((const float4*)g_M)[idx];
    }
    __syncthreads();

    // flat gather: 8192 float4 slots (rows 0..127 = XI, 128..255 = XU);
    // each warp loads one contiguous 512B row per iter, 16 independent iters.
#pragma unroll
    for (int it = 0; it < 16; it++) {
        int idx = it * 512 + tid;
        int row = idx >> 5, f4 = idx & 31;
        if (row < 128) {
            int node = Ndi[row];
            float4 v = ((const float4*)(g_agg + (size_t)node * DIM))[f4];
            float* p = &XIs[row * S + 4 * f4];
            p[0] = tf32r(v.x); p[1] = tf32r(v.y); p[2] = tf32r(v.z); p[3] = tf32r(v.w);
        } else {
            int node = Ndu[row - 128];
            float4 v = ((const float4*)(g_agg + (size_t)node * DIM))[f4];
            *(float4*)&XUs[(row - 128) * S + 4 * f4] = v;
        }
    }
    __syncthreads();

    // clear mask for this block's nodes (restores invariant for next call)
    if (tid < 128) {
        g_mask[Ndi[tid]] = 0;
        g_mask[Ndu[tid]] = 0;
    }

    // warp tile: rows m0..m0+31, cols j0..j0+31
    int m0 = (warp & 3) * 32, j0 = (warp >> 2) * 32;
    float acc[2][4][4];
#pragma unroll
    for (int mi = 0; mi < 2; mi++)
#pragma unroll
        for (int ni = 0; ni < 4; ni++)
#pragma unroll
            for (int q = 0; q < 4; q++) acc[mi][ni][q] = 0.f;

#pragma unroll
    for (int k0 = 0; k0 < DIM; k0 += 8) {
        uint32_t a[2][4], b[4][2];
#pragma unroll
        for (int mi = 0; mi < 2; mi++) {
            const float* ap = XIs + (m0 + 16 * mi + g) * S + k0 + t;
            a[mi][0] = __float_as_uint(ap[0]);
            a[mi][1] = __float_as_uint(ap[8 * S]);
            a[mi][2] = __float_as_uint(ap[4]);
            a[mi][3] = __float_as_uint(ap[8 * S + 4]);
        }
#pragma unroll
        for (int ni = 0; ni < 4; ni++) {
            const float* bp = Msm + (j0 + 8 * ni + g) * S + k0 + t;
            b[ni][0] = __float_as_uint(bp[0]);
            b[ni][1] = __float_as_uint(bp[4]);
        }
#pragma unroll
        for (int mi = 0; mi < 2; mi++)
#pragma unroll
            for (int ni = 0; ni < 4; ni++)
                asm volatile(
                    "mma.sync.aligned.m16n8k8.row.col.f32.tf32.tf32.f32 "
                    "{%0,%1,%2,%3}, {%4,%5,%6,%7}, {%8,%9}, {%0,%1,%2,%3};"
                    : "+f"(acc[mi][ni][0]), "+f"(acc[mi][ni][1]),
                      "+f"(acc[mi][ni][2]), "+f"(acc[mi][ni][3])
                    : "r"(a[mi][0]), "r"(a[mi][1]), "r"(a[mi][2]), "r"(a[mi][3]),
                      "r"(b[ni][0]), "r"(b[ni][1]));
    }

    // epilogue: p_row = sum_j in warp tile of [xu*(y+v) + v*xi]; reduce over t
    int nw = warp >> 2;
#pragma unroll
    for (int mi = 0; mi < 2; mi++) {
        int r_lo = m0 + 16 * mi + g;
        int r_hi = r_lo + 8;
        float plo = 0.f, phi = 0.f;
#pragma unroll
        for (int ni = 0; ni < 4; ni++) {
            int j = j0 + 8 * ni + 2 * t;
            float2 vl  = *(const float2*)&Vv[j];
            float2 xul = *(const float2*)&XUs[r_lo * S + j];
            float2 xuh = *(const float2*)&XUs[r_hi * S + j];
            float2 xil = *(const float2*)&XIs[r_lo * S + j];
            float2 xih = *(const float2*)&XIs[r_hi * S + j];
            plo += xul.x * (acc[mi][ni][0] + vl.x) + xul.y * (acc[mi][ni][1] + vl.y)
                 + vl.x * xil.x + vl.y * xil.y;
            phi += xuh.x * (acc[mi][ni][2] + vl.x) + xuh.y * (acc[mi][ni][3] + vl.y)
                 + vl.x * xih.x + vl.y * xih.y;
        }
        plo += __shfl_xor_sync(0xffffffffu, plo, 1);
        plo += __shfl_xor_sync(0xffffffffu, plo, 2);
        phi += __shfl_xor_sync(0xffffffffu, phi, 1);
        phi += __shfl_xor_sync(0xffffffffu, phi, 2);
        if (t == 0) {
            Part[r_lo * 4 + nw] = plo;
            Part[r_hi * 4 + nw] = phi;
        }
    }
    __syncthreads();

    if (tid < BPB) {
        float r = Part[tid * 4 + 0] + Part[tid * 4 + 1]
                + Part[tid * 4 + 2] + Part[tid * 4 + 3];
        out[base + tid] = r + g_c;
    }
}

// ---------------- launch (fork/join: k_m overlaps mark+edge) -----------------
extern "C" void kernel_launch(void* const* d_in, const int* in_sizes, int n_in,
                              void* d_out, int out_size) {
    const int*   ui   = (const int*)d_in[0];
    const int*   ii   = (const int*)d_in[1];
    const float* uemb = (const float*)d_in[2];
    const float* iemb = (const float*)d_in[3];
    const float* W    = (const float*)d_in[4];
    const float* b    = (const float*)d_in[5];
    const int*   ei   = (const int*)d_in[6];
    const int*   src  = ei;
    const int*   dst  = ei + NUM_EDGES;
    float*       out  = (float*)d_out;

    static cudaStream_t side = nullptr;
    static cudaEvent_t evFork = nullptr, evJoin = nullptr;
    if (!side) {
        cudaStreamCreateWithFlags(&side, cudaStreamNonBlocking);
        cudaEventCreateWithFlags(&evFork, cudaEventDisableTiming);
        cudaEventCreateWithFlags(&evJoin, cudaEventDisableTiming);
        cudaFuncSetAttribute(k_pairs, cudaFuncAttributeMaxDynamicSharedMemorySize, SMEM_K3);
    }

    // fork: side stream computes M/v/c while main stream does mark+edges
    cudaEventRecord(evFork, 0);
    cudaStreamWaitEvent(side, evFork, 0);
    k_m<<<DIM, DIM, 0, side>>>(W, b);
    cudaEventRecord(evJoin, side);

    k_mark<<<MARKBLOCKS, 256>>>(ui, ii);
    k_edge<<<(NUM_EDGES + 255) / 256, 256>>>(src, dst, uemb, iemb);

    cudaStreamWaitEvent(0, evJoin, 0);   // join before k_pairs (needs g_M/g_v/g_c)
    k_pairs<<<BATCH / BPB, 512, SMEM_K3>>>(ui, ii, out);
}

// round 13
// speedup vs baseline: 1.1211x; 1.1211x over previous
#include <cuda_runtime.h>
#include <cuda_bf16.h>
#include <cstdint>

#define NUM_USERS 200000
#define NUM_ITEMS 100000
#define NUM_NODES (NUM_USERS + NUM_ITEMS)
#define NUM_EDGES 600000
#define DIM 128
#define BATCH 16384
#define BPB 128
#define S 132   // smem row stride (floats): conflict-free fragment access

// ---------------- scratch (static device globals) ---------------------------
// INVARIANT: g_mask is all-zero at entry to every kernel_launch call.
__device__ __align__(16) float g_agg[(size_t)NUM_NODES * DIM];
__device__ __align__(16) unsigned char g_mask[NUM_NODES];
__device__ __align__(16) float g_M[DIM * DIM];      // W^T W, tf32-rounded (symmetric)
__device__ __align__(16) float g_v[DIM];            // W^T b (fp32)
__device__ float g_c;                               // b.b

__device__ __forceinline__ float tf32r(float x) {
    unsigned u = __float_as_uint(x);
    u = (u + 0x1000u) & 0xFFFFE000u;
    return __uint_as_float(u);
}
__device__ __forceinline__ uint32_t smem_u32(const void* p) {
    uint32_t a;
    asm("{ .reg .u64 t; cvta.to.shared.u64 t, %1; cvt.u32.u64 %0, t; }" : "=r"(a) : "l"(p));
    return a;
}
__device__ __forceinline__ void cp16(uint32_t saddr, const void* gp) {
    size_t ga = __cvta_generic_to_global(gp);
    asm volatile("cp.async.cg.shared.global [%0], [%1], 16;" :: "r"(saddr), "l"(ga) : "memory");
}
#define CP_COMMIT() asm volatile("cp.async.commit_group;" ::: "memory")
#define CP_WAIT0()  asm volatile("cp.async.wait_group 0;" ::: "memory")

// ---------------- K_m (side stream): M = W^T W (tf32), v = W^T b, c = b.b ----
__global__ void k_m(const float* __restrict__ W, const float* __restrict__ b) {
    int r = blockIdx.x;      // 0..127
    int c = threadIdx.x;     // 0..127
    float a0 = 0.f, a1 = 0.f, a2 = 0.f, a3 = 0.f;
#pragma unroll
    for (int j = 0; j < DIM; j += 4) {
        a0 += __ldg(&W[(j + 0) * DIM + r]) * __ldg(&W[(j + 0) * DIM + c]);
        a1 += __ldg(&W[(j + 1) * DIM + r]) * __ldg(&W[(j + 1) * DIM + c]);
        a2 += __ldg(&W[(j + 2) * DIM + r]) * __ldg(&W[(j + 2) * DIM + c]);
        a3 += __ldg(&W[(j + 3) * DIM + r]) * __ldg(&W[(j + 3) * DIM + c]);
    }
    g_M[r * DIM + c] = tf32r((a0 + a1) + (a2 + a3));
    if (r == 0) {
        float vv = 0.f;
#pragma unroll 8
        for (int j = 0; j < DIM; j++) vv += __ldg(&b[j]) * __ldg(&W[j * DIM + c]);
        g_v[c] = vv;
        if (c == 0) {
            float s = 0.f;
#pragma unroll 8
            for (int j = 0; j < DIM; j++) s += b[j] * b[j];
            g_c = s;
        }
    }
}

// ---------------- K_mark (main stream): mark needed nodes + zero agg rows ----
#define MARKBLOCKS (2 * BATCH / 32)
__global__ void k_mark(const int* __restrict__ ui, const int* __restrict__ ii) {
    int warp = threadIdx.x >> 5, lane = threadIdx.x & 31;
    int rowbase = blockIdx.x * 32 + warp * 4;
    int nodes[4];
#pragma unroll
    for (int q = 0; q < 4; q++) {
        int ref = rowbase + q;
        nodes[q] = (ref < BATCH) ? __ldg(&ui[ref])
                                 : (NUM_USERS + __ldg(&ii[ref - BATCH]));
    }
    const float4 z = make_float4(0.f, 0.f, 0.f, 0.f);
#pragma unroll
    for (int q = 0; q < 4; q++)
        ((float4*)(g_agg + (size_t)nodes[q] * DIM))[lane] = z;
    if (lane == 0) {
#pragma unroll
        for (int q = 0; q < 4; q++) g_mask[nodes[q]] = 1;
    }
}

// ---------------- K1: scan edges, gather + vectorized scatter-add ------------
__global__ void k_edge(const int* __restrict__ src, const int* __restrict__ dst,
                       const float* __restrict__ uemb, const float* __restrict__ iemb) {
    int e = blockIdx.x * blockDim.x + threadIdx.x;
    int lane = threadIdx.x & 31;
    bool pass = false;
    int d = 0, s = 0;
    if (e < NUM_EDGES) {
        d = dst[e];
        pass = (g_mask[d] != 0);
        if (pass) s = src[e];
    }
    unsigned m = __ballot_sync(0xffffffffu, pass);
    while (m) {
        int bit = __ffs(m) - 1;
        m &= m - 1;
        int ds = __shfl_sync(0xffffffffu, d, bit);
        int ss = __shfl_sync(0xffffffffu, s, bit);
        const float* sp = (ss < NUM_USERS)
                            ? (uemb + (size_t)ss * DIM)
                            : (iemb + (size_t)(ss - NUM_USERS) * DIM);
        float4 v = ((const float4*)sp)[lane];
        float* a = g_agg + (size_t)ds * DIM + lane * 4;
        asm volatile("red.global.add.v4.f32 [%0], {%1, %2, %3, %4};"
                     :: "l"(a), "f"(v.x), "f"(v.y), "f"(v.z), "f"(v.w)
                     : "memory");
    }
}

// ---------------- K2: mma.sync tf32 GEMM + fused bilinear epilogue -----------
// Staging via cp.async (zero register pressure, full MLP). tf32 rounding of XI
// done by an in-smem pass after the copies land.
#define MS_OFF   0
#define XI_OFF   (DIM * S * 4)
#define XU_OFF   (2 * DIM * S * 4)
#define VV_OFF   (3 * DIM * S * 4)
#define NDI_OFF  (VV_OFF + 512)
#define NDU_OFF  (NDI_OFF + 512)
#define PART_OFF (NDU_OFF + 512)
#define SMEM_K3  (PART_OFF + 2048)

__global__ void __launch_bounds__(512) k_pairs(
    const int* __restrict__ ui, const int* __restrict__ ii,
    float* __restrict__ out)
{
    extern __shared__ char sm[];
    uint32_t sbase = smem_u32(sm);
    float* Msm  = (float*)(sm + MS_OFF);    // Msm[j][k] (symmetric M)
    float* XIs  = (float*)(sm + XI_OFF);    // XIs[i][k], tf32-rounded in pass 2
    float* XUs  = (float*)(sm + XU_OFF);    // XUs[i][k], fp32
    float* Vv   = (float*)(sm + VV_OFF);
    int*   Ndi  = (int*)(sm + NDI_OFF);
    int*   Ndu  = (int*)(sm + NDU_OFF);
    float* Part = (float*)(sm + PART_OFF);  // [128][4]

    int tid = threadIdx.x, warp = tid >> 5, lane = tid & 31;
    int base = blockIdx.x * BPB;
    int g = lane >> 2, t = lane & 3;

    // stage node indices + v (needed before the async gather)
    if (tid < 128) {
        Ndi[tid] = NUM_USERS + __ldg(&ii[base + tid]);
        Ndu[tid] = __ldg(&ui[base + tid]);
        Vv[tid]  = g_v[tid];
    }
    __syncthreads();

    // cp.async M restride: 4096 16B chunks (8 per thread)
#pragma unroll
    for (int i = tid; i < DIM * DIM / 4; i += 512) {
        int r = i >> 5, c4 = i & 31;
        cp16(sbase + MS_OFF + (r * S + 4 * c4) * 4, (const char*)g_M + (r * DIM + 4 * c4) * 4);
    }
    // cp.async gather: 8192 16B chunks; warp w loads one 512B row per iter
#pragma unroll
    for (int it = 0; it < 16; it++) {
        int idx = it * 512 + tid;
        int row = idx >> 5, f4 = idx & 31;
        if (row < 128) {
            cp16(sbase + XI_OFF + (row * S + 4 * f4) * 4,
                 g_agg + (size_t)Ndi[row] * DIM + 4 * f4);
        } else {
            int rr = row - 128;
            cp16(sbase + XU_OFF + (rr * S + 4 * f4) * 4,
                 g_agg + (size_t)Ndu[rr] * DIM + 4 * f4);
        }
    }
    CP_COMMIT();
    CP_WAIT0();
    __syncthreads();

    // in-smem tf32 rounding pass on XIs (RN); also clear mask (invariant)
#pragma unroll
    for (int i = tid; i < DIM * DIM / 4; i += 512) {
        int row = i >> 5, f4 = i & 31;
        float4* p = (float4*)&XIs[row * S + 4 * f4];
        float4 v = *p;
        v.x = tf32r(v.x); v.y = tf32r(v.y); v.z = tf32r(v.z); v.w = tf32r(v.w);
        *p = v;
    }
    if (tid < 128) {
        g_mask[Ndi[tid]] = 0;
        g_mask[Ndu[tid]] = 0;
    }
    __syncthreads();

    // warp tile: rows m0..m0+31, cols j0..j0+31
    int m0 = (warp & 3) * 32, j0 = (warp >> 2) * 32;
    float acc[2][4][4];
#pragma unroll
    for (int mi = 0; mi < 2; mi++)
#pragma unroll
        for (int ni = 0; ni < 4; ni++)
#pragma unroll
            for (int q = 0; q < 4; q++) acc[mi][ni][q] = 0.f;

#pragma unroll
    for (int k0 = 0; k0 < DIM; k0 += 8) {
        uint32_t a[2][4], b[4][2];
#pragma unroll
        for (int mi = 0; mi < 2; mi++) {
            const float* ap = XIs + (m0 + 16 * mi + g) * S + k0 + t;
            a[mi][0] = __float_as_uint(ap[0]);
            a[mi][1] = __float_as_uint(ap[8 * S]);
            a[mi][2] = __float_as_uint(ap[4]);
            a[mi][3] = __float_as_uint(ap[8 * S + 4]);
        }
#pragma unroll
        for (int ni = 0; ni < 4; ni++) {
            const float* bp = Msm + (j0 + 8 * ni + g) * S + k0 + t;
            b[ni][0] = __float_as_uint(bp[0]);
            b[ni][1] = __float_as_uint(bp[4]);
        }
#pragma unroll
        for (int mi = 0; mi < 2; mi++)
#pragma unroll
            for (int ni = 0; ni < 4; ni++)
                asm volatile(
                    "mma.sync.aligned.m16n8k8.row.col.f32.tf32.tf32.f32 "
                    "{%0,%1,%2,%3}, {%4,%5,%6,%7}, {%8,%9}, {%0,%1,%2,%3};"
                    : "+f"(acc[mi][ni][0]), "+f"(acc[mi][ni][1]),
                      "+f"(acc[mi][ni][2]), "+f"(acc[mi][ni][3])
                    : "r"(a[mi][0]), "r"(a[mi][1]), "r"(a[mi][2]), "r"(a[mi][3]),
                      "r"(b[ni][0]), "r"(b[ni][1]));
    }

    // epilogue: p_row = sum_j in warp tile of [xu*(y+v) + v*xi]; reduce over t
    int nw = warp >> 2;
#pragma unroll
    for (int mi = 0; mi < 2; mi++) {
        int r_lo = m0 + 16 * mi + g;
        int r_hi = r_lo + 8;
        float plo = 0.f, phi = 0.f;
#pragma unroll
        for (int ni = 0; ni < 4; ni++) {
            int j = j0 + 8 * ni + 2 * t;
            float2 vl  = *(const float2*)&Vv[j];
            float2 xul = *(const float2*)&XUs[r_lo * S + j];
            float2 xuh = *(const float2*)&XUs[r_hi * S + j];
            float2 xil = *(const float2*)&XIs[r_lo * S + j];
            float2 xih = *(const float2*)&XIs[r_hi * S + j];
            plo += xul.x * (acc[mi][ni][0] + vl.x) + xul.y * (acc[mi][ni][1] + vl.y)
                 + vl.x * xil.x + vl.y * xil.y;
            phi += xuh.x * (acc[mi][ni][2] + vl.x) + xuh.y * (acc[mi][ni][3] + vl.y)
                 + vl.x * xih.x + vl.y * xih.y;
        }
        plo += __shfl_xor_sync(0xffffffffu, plo, 1);
        plo += __shfl_xor_sync(0xffffffffu, plo, 2);
        phi += __shfl_xor_sync(0xffffffffu, phi, 1);
        phi += __shfl_xor_sync(0xffffffffu, phi, 2);
        if (t == 0) {
            Part[r_lo * 4 + nw] = plo;
            Part[r_hi * 4 + nw] = phi;
        }
    }
    __syncthreads();

    if (tid < BPB) {
        float r = Part[tid * 4 + 0] + Part[tid * 4 + 1]
                + Part[tid * 4 + 2] + Part[tid * 4 + 3];
        out[base + tid] = r + g_c;
    }
}

// ---------------- launch (fork/join: k_m overlaps mark+edge) -----------------
extern "C" void kernel_launch(void* const* d_in, const int* in_sizes, int n_in,
                              void* d_out, int out_size) {
    const int*   ui   = (const int*)d_in[0];
    const int*   ii   = (const int*)d_in[1];
    const float* uemb = (const float*)d_in[2];
    const float* iemb = (const float*)d_in[3];
    const float* W    = (const float*)d_in[4];
    const float* b    = (const float*)d_in[5];
    const int*   ei   = (const int*)d_in[6];
    const int*   src  = ei;
    const int*   dst  = ei + NUM_EDGES;
    float*       out  = (float*)d_out;

    static cudaStream_t side = nullptr;
    static cudaEvent_t evFork = nullptr, evJoin = nullptr;
    if (!side) {
        cudaStreamCreateWithFlags(&side, cudaStreamNonBlocking);
        cudaEventCreateWithFlags(&evFork, cudaEventDisableTiming);
        cudaEventCreateWithFlags(&evJoin, cudaEventDisableTiming);
        cudaFuncSetAttribute(k_pairs, cudaFuncAttributeMaxDynamicSharedMemorySize, SMEM_K3);
    }

    // fork: side stream computes M/v/c while main stream does mark+edges
    cudaEventRecord(evFork, 0);
    cudaStreamWaitEvent(side, evFork, 0);
    k_m<<<DIM, DIM, 0, side>>>(W, b);
    cudaEventRecord(evJoin, side);

    k_mark<<<MARKBLOCKS, 256>>>(ui, ii);
    k_edge<<<(NUM_EDGES + 255) / 256, 256>>>(src, dst, uemb, iemb);

    cudaStreamWaitEvent(0, evJoin, 0);   // join before k_pairs (needs g_M/g_v/g_c)
    k_pairs<<<BATCH / BPB, 512, SMEM_K3>>>(ui, ii, out);
}

// round 14
// speedup vs baseline: 1.1862x; 1.0581x over previous
#include <cuda_runtime.h>
#include <cuda_bf16.h>
#include <cstdint>

#define NUM_USERS 200000
#define NUM_ITEMS 100000
#define NUM_NODES (NUM_USERS + NUM_ITEMS)
#define NUM_EDGES 600000
#define DIM 128
#define BATCH 16384
#define BPB 128
#define S 132   // smem row stride (floats): conflict-free fragment access

// ---------------- scratch (static device globals) ---------------------------
// INVARIANT: g_mask is all-zero at entry to every kernel_launch call.
__device__ __align__(16) float g_agg[(size_t)NUM_NODES * DIM];
__device__ __align__(16) unsigned char g_mask[NUM_NODES];
__device__ __align__(16) float g_M[DIM * DIM];      // W^T W, tf32-rounded (symmetric)
__device__ __align__(16) float g_v[DIM];            // W^T b (fp32)
__device__ float g_c;                               // b.b

__device__ __forceinline__ float tf32r(float x) {
    unsigned u = __float_as_uint(x);
    u = (u + 0x1000u) & 0xFFFFE000u;
    return __uint_as_float(u);
}
__device__ __forceinline__ uint32_t smem_u32(const void* p) {
    uint32_t a;
    asm("{ .reg .u64 t; cvta.to.shared.u64 t, %1; cvt.u32.u64 %0, t; }" : "=r"(a) : "l"(p));
    return a;
}
__device__ __forceinline__ void cp16(uint32_t saddr, const void* gp) {
    size_t ga = __cvta_generic_to_global(gp);
    asm volatile("cp.async.cg.shared.global [%0], [%1], 16;" :: "r"(saddr), "l"(ga) : "memory");
}
#define CP_COMMIT()  asm volatile("cp.async.commit_group;" ::: "memory")
#define CP_WAIT(n)   asm volatile("cp.async.wait_group %0;" :: "n"(n) : "memory")

// ---------------- K_m (side stream): M = W^T W (tf32), v = W^T b, c = b.b ----
__global__ void k_m(const float* __restrict__ W, const float* __restrict__ b) {
    int r = blockIdx.x;      // 0..127
    int c = threadIdx.x;     // 0..127
    float a0 = 0.f, a1 = 0.f, a2 = 0.f, a3 = 0.f;
#pragma unroll
    for (int j = 0; j < DIM; j += 4) {
        a0 += __ldg(&W[(j + 0) * DIM + r]) * __ldg(&W[(j + 0) * DIM + c]);
        a1 += __ldg(&W[(j + 1) * DIM + r]) * __ldg(&W[(j + 1) * DIM + c]);
        a2 += __ldg(&W[(j + 2) * DIM + r]) * __ldg(&W[(j + 2) * DIM + c]);
        a3 += __ldg(&W[(j + 3) * DIM + r]) * __ldg(&W[(j + 3) * DIM + c]);
    }
    g_M[r * DIM + c] = tf32r((a0 + a1) + (a2 + a3));
    if (r == 0) {
        float vv = 0.f;
#pragma unroll 8
        for (int j = 0; j < DIM; j++) vv += __ldg(&b[j]) * __ldg(&W[j * DIM + c]);
        g_v[c] = vv;
        if (c == 0) {
            float s = 0.f;
#pragma unroll 8
            for (int j = 0; j < DIM; j++) s += b[j] * b[j];
            g_c = s;
        }
    }
}

// ---------------- K_mark (main stream): mark needed nodes + zero agg rows ----
#define MARKBLOCKS (2 * BATCH / 32)
__global__ void k_mark(const int* __restrict__ ui, const int* __restrict__ ii) {
    int warp = threadIdx.x >> 5, lane = threadIdx.x & 31;
    int rowbase = blockIdx.x * 32 + warp * 4;
    int nodes[4];
#pragma unroll
    for (int q = 0; q < 4; q++) {
        int ref = rowbase + q;
        nodes[q] = (ref < BATCH) ? __ldg(&ui[ref])
                                 : (NUM_USERS + __ldg(&ii[ref - BATCH]));
    }
    const float4 z = make_float4(0.f, 0.f, 0.f, 0.f);
#pragma unroll
    for (int q = 0; q < 4; q++)
        ((float4*)(g_agg + (size_t)nodes[q] * DIM))[lane] = z;
    if (lane == 0) {
#pragma unroll
        for (int q = 0; q < 4; q++) g_mask[nodes[q]] = 1;
    }
}

// ---------------- K1: scan edges, gather + vectorized scatter-add ------------
__global__ void k_edge(const int* __restrict__ src, const int* __restrict__ dst,
                       const float* __restrict__ uemb, const float* __restrict__ iemb) {
    int e = blockIdx.x * blockDim.x + threadIdx.x;
    int lane = threadIdx.x & 31;
    bool pass = false;
    int d = 0, s = 0;
    if (e < NUM_EDGES) {
        d = dst[e];
        pass = (g_mask[d] != 0);
        if (pass) s = src[e];
    }
    unsigned m = __ballot_sync(0xffffffffu, pass);
    while (m) {
        int bit = __ffs(m) - 1;
        m &= m - 1;
        int ds = __shfl_sync(0xffffffffu, d, bit);
        int ss = __shfl_sync(0xffffffffu, s, bit);
        const float* sp = (ss < NUM_USERS)
                            ? (uemb + (size_t)ss * DIM)
                            : (iemb + (size_t)(ss - NUM_USERS) * DIM);
        float4 v = ((const float4*)sp)[lane];
        float* a = g_agg + (size_t)ds * DIM + lane * 4;
        asm volatile("red.global.add.v4.f32 [%0], {%1, %2, %3, %4};"
                     :: "l"(a), "f"(v.x), "f"(v.y), "f"(v.z), "f"(v.w)
                     : "memory");
    }
}

// ---------------- K2: mma.sync tf32 GEMM + fused bilinear epilogue -----------
// Pipelined cp.async staging:
//   group1 XI -> wait(2) -> round XI (M in flight)
//   group2 M  -> wait(1) -> MMA loop (XU in flight)
//   group3 XU -> wait(0) -> epilogue
#define MS_OFF   0
#define XI_OFF   (DIM * S * 4)
#define XU_OFF   (2 * DIM * S * 4)
#define VV_OFF   (3 * DIM * S * 4)
#define NDI_OFF  (VV_OFF + 512)
#define NDU_OFF  (NDI_OFF + 512)
#define PART_OFF (NDU_OFF + 512)
#define SMEM_K3  (PART_OFF + 2048)

__global__ void __launch_bounds__(512) k_pairs(
    const int* __restrict__ ui, const int* __restrict__ ii,
    float* __restrict__ out)
{
    extern __shared__ char sm[];
    uint32_t sbase = smem_u32(sm);
    float* Msm  = (float*)(sm + MS_OFF);    // Msm[j][k] (symmetric M)
    float* XIs  = (float*)(sm + XI_OFF);    // XIs[i][k], tf32-rounded
    float* XUs  = (float*)(sm + XU_OFF);    // XUs[i][k], fp32
    float* Vv   = (float*)(sm + VV_OFF);
    int*   Ndi  = (int*)(sm + NDI_OFF);
    int*   Ndu  = (int*)(sm + NDU_OFF);
    float* Part = (float*)(sm + PART_OFF);  // [128][4]

    int tid = threadIdx.x, warp = tid >> 5, lane = tid & 31;
    int base = blockIdx.x * BPB;
    int g = lane >> 2, t = lane & 3;

    // stage node indices + v (needed before the async gather)
    if (tid < 128) {
        Ndi[tid] = NUM_USERS + __ldg(&ii[base + tid]);
        Ndu[tid] = __ldg(&ui[base + tid]);
        Vv[tid]  = g_v[tid];
    }
    __syncthreads();

    // group 1: XI gather (4096 chunks, 8/thread; warp -> one 512B row/iter)
#pragma unroll
    for (int it = 0; it < 8; it++) {
        int idx = it * 512 + tid;
        int row = idx >> 5, f4 = idx & 31;
        cp16(sbase + XI_OFF + (row * S + 4 * f4) * 4,
             g_agg + (size_t)Ndi[row] * DIM + 4 * f4);
    }
    CP_COMMIT();
    // group 2: M restride (4096 chunks, 8/thread)
#pragma unroll
    for (int i = tid; i < DIM * DIM / 4; i += 512) {
        int r = i >> 5, c4 = i & 31;
        cp16(sbase + MS_OFF + (r * S + 4 * c4) * 4,
             (const char*)g_M + (r * DIM + 4 * c4) * 4);
    }
    CP_COMMIT();
    // group 3: XU gather
#pragma unroll
    for (int it = 0; it < 8; it++) {
        int idx = it * 512 + tid;
        int row = idx >> 5, f4 = idx & 31;
        cp16(sbase + XU_OFF + (row * S + 4 * f4) * 4,
             g_agg + (size_t)Ndu[row] * DIM + 4 * f4);
    }
    CP_COMMIT();

    // wait XI; round it to tf32 (RN) while M/XU are still in flight
    CP_WAIT(2);
    __syncthreads();
#pragma unroll
    for (int i = tid; i < DIM * DIM / 4; i += 512) {
        int row = i >> 5, f4 = i & 31;
        float4* p = (float4*)&XIs[row * S + 4 * f4];
        float4 v = *p;
        v.x = tf32r(v.x); v.y = tf32r(v.y); v.z = tf32r(v.z); v.w = tf32r(v.w);
        *p = v;
    }
    if (tid < 128) {            // restore mask invariant
        g_mask[Ndi[tid]] = 0;
        g_mask[Ndu[tid]] = 0;
    }
    // wait M; MMA can start (XU still in flight)
    CP_WAIT(1);
    __syncthreads();

    // warp tile: rows m0..m0+31, cols j0..j0+31
    int m0 = (warp & 3) * 32, j0 = (warp >> 2) * 32;
    float acc[2][4][4];
#pragma unroll
    for (int mi = 0; mi < 2; mi++)
#pragma unroll
        for (int ni = 0; ni < 4; ni++)
#pragma unroll
            for (int q = 0; q < 4; q++) acc[mi][ni][q] = 0.f;

#pragma unroll
    for (int k0 = 0; k0 < DIM; k0 += 8) {
        uint32_t a[2][4], b[4][2];
#pragma unroll
        for (int mi = 0; mi < 2; mi++) {
            const float* ap = XIs + (m0 + 16 * mi + g) * S + k0 + t;
            a[mi][0] = __float_as_uint(ap[0]);
            a[mi][1] = __float_as_uint(ap[8 * S]);
            a[mi][2] = __float_as_uint(ap[4]);
            a[mi][3] = __float_as_uint(ap[8 * S + 4]);
        }
#pragma unroll
        for (int ni = 0; ni < 4; ni++) {
            const float* bp = Msm + (j0 + 8 * ni + g) * S + k0 + t;
            b[ni][0] = __float_as_uint(bp[0]);
            b[ni][1] = __float_as_uint(bp[4]);
        }
#pragma unroll
        for (int mi = 0; mi < 2; mi++)
#pragma unroll
            for (int ni = 0; ni < 4; ni++)
                asm volatile(
                    "mma.sync.aligned.m16n8k8.row.col.f32.tf32.tf32.f32 "
                    "{%0,%1,%2,%3}, {%4,%5,%6,%7}, {%8,%9}, {%0,%1,%2,%3};"
                    : "+f"(acc[mi][ni][0]), "+f"(acc[mi][ni][1]),
                      "+f"(acc[mi][ni][2]), "+f"(acc[mi][ni][3])
                    : "r"(a[mi][0]), "r"(a[mi][1]), "r"(a[mi][2]), "r"(a[mi][3]),
                      "r"(b[ni][0]), "r"(b[ni][1]));
    }

    // wait XU before epilogue
    CP_WAIT(0);
    __syncthreads();

    // epilogue: p_row = sum_j in warp tile of [xu*(y+v) + v*xi]; reduce over t
    int nw = warp >> 2;
#pragma unroll
    for (int mi = 0; mi < 2; mi++) {
        int r_lo = m0 + 16 * mi + g;
        int r_hi = r_lo + 8;
        float plo = 0.f, phi = 0.f;
#pragma unroll
        for (int ni = 0; ni < 4; ni++) {
            int j = j0 + 8 * ni + 2 * t;
            float2 vl  = *(const float2*)&Vv[j];
            float2 xul = *(const float2*)&XUs[r_lo * S + j];
            float2 xuh = *(const float2*)&XUs[r_hi * S + j];
            float2 xil = *(const float2*)&XIs[r_lo * S + j];
            float2 xih = *(const float2*)&XIs[r_hi * S + j];
            plo += xul.x * (acc[mi][ni][0] + vl.x) + xul.y * (acc[mi][ni][1] + vl.y)
                 + vl.x * xil.x + vl.y * xil.y;
            phi += xuh.x * (acc[mi][ni][2] + vl.x) + xuh.y * (acc[mi][ni][3] + vl.y)
                 + vl.x * xih.x + vl.y * xih.y;
        }
        plo += __shfl_xor_sync(0xffffffffu, plo, 1);
        plo += __shfl_xor_sync(0xffffffffu, plo, 2);
        phi += __shfl_xor_sync(0xffffffffu, phi, 1);
        phi += __shfl_xor_sync(0xffffffffu, phi, 2);
        if (t == 0) {
            Part[r_lo * 4 + nw] = plo;
            Part[r_hi * 4 + nw] = phi;
        }
    }
    __syncthreads();

    if (tid < BPB) {
        float r = Part[tid * 4 + 0] + Part[tid * 4 + 1]
                + Part[tid * 4 + 2] + Part[tid * 4 + 3];
        out[base + tid] = r + g_c;
    }
}

// ---------------- launch (fork/join: k_m overlaps mark+edge) -----------------
extern "C" void kernel_launch(void* const* d_in, const int* in_sizes, int n_in,
                              void* d_out, int out_size) {
    const int*   ui   = (const int*)d_in[0];
    const int*   ii   = (const int*)d_in[1];
    const float* uemb = (const float*)d_in[2];
    const float* iemb = (const float*)d_in[3];
    const float* W    = (const float*)d_in[4];
    const float* b    = (const float*)d_in[5];
    const int*   ei   = (const int*)d_in[6];
    const int*   src  = ei;
    const int*   dst  = ei + NUM_EDGES;
    float*       out  = (float*)d_out;

    static cudaStream_t side = nullptr;
    static cudaEvent_t evFork = nullptr, evJoin = nullptr;
    if (!side) {
        cudaStreamCreateWithFlags(&side, cudaStreamNonBlocking);
        cudaEventCreateWithFlags(&evFork, cudaEventDisableTiming);
        cudaEventCreateWithFlags(&evJoin, cudaEventDisableTiming);
        cudaFuncSetAttribute(k_pairs, cudaFuncAttributeMaxDynamicSharedMemorySize, SMEM_K3);
    }

    // fork: side stream computes M/v/c while main stream does mark+edges
    cudaEventRecord(evFork, 0);
    cudaStreamWaitEvent(side, evFork, 0);
    k_m<<<DIM, DIM, 0, side>>>(W, b);
    cudaEventRecord(evJoin, side);

    k_mark<<<MARKBLOCKS, 256>>>(ui, ii);
    k_edge<<<(NUM_EDGES + 255) / 256, 256>>>(src, dst, uemb, iemb);

    cudaStreamWaitEvent(0, evJoin, 0);   // join before k_pairs (needs g_M/g_v/g_c)
    k_pairs<<<BATCH / BPB, 512, SMEM_K3>>>(ui, ii, out);
}

// round 15
// speedup vs baseline: 1.1922x; 1.0050x over previous
#include <cuda_runtime.h>
#include <cuda_bf16.h>
#include <cstdint>

#define NUM_USERS 200000
#define NUM_ITEMS 100000
#define NUM_NODES (NUM_USERS + NUM_ITEMS)
#define NUM_EDGES 600000
#define DIM 128
#define BATCH 16384
#define BPB 128
#define S 132   // smem row stride (floats): conflict-free fragment access

// ---------------- scratch (static device globals) ---------------------------
// INVARIANT: g_mask is all-zero at entry to every kernel_launch call.
__device__ __align__(16) float g_agg[(size_t)NUM_NODES * DIM];
__device__ __align__(16) unsigned char g_mask[NUM_NODES];
__device__ __align__(16) float g_M[DIM * DIM];      // W^T W, tf32-rounded (symmetric)
__device__ __align__(16) float g_v[DIM];            // W^T b (fp32)
__device__ float g_c;                               // b.b

__device__ __forceinline__ float tf32r(float x) {
    unsigned u = __float_as_uint(x);
    u = (u + 0x1000u) & 0xFFFFE000u;
    return __uint_as_float(u);
}
__device__ __forceinline__ uint32_t smem_u32(const void* p) {
    uint32_t a;
    asm("{ .reg .u64 t; cvta.to.shared.u64 t, %1; cvt.u32.u64 %0, t; }" : "=r"(a) : "l"(p));
    return a;
}
__device__ __forceinline__ void cp16(uint32_t saddr, const void* gp) {
    size_t ga = __cvta_generic_to_global(gp);
    asm volatile("cp.async.cg.shared.global [%0], [%1], 16;" :: "r"(saddr), "l"(ga) : "memory");
}
#define CP_COMMIT()  asm volatile("cp.async.commit_group;" ::: "memory")
#define CP_WAIT(n)   asm volatile("cp.async.wait_group %0;" :: "n"(n) : "memory")
__device__ __forceinline__ void red4(float* a, float4 v) {
    asm volatile("red.global.add.v4.f32 [%0], {%1, %2, %3, %4};"
                 :: "l"(a), "f"(v.x), "f"(v.y), "f"(v.z), "f"(v.w) : "memory");
}

// ---------------- K_m (side stream): M = W^T W (tf32), v = W^T b, c = b.b ----
__global__ void k_m(const float* __restrict__ W, const float* __restrict__ b) {
    int r = blockIdx.x;      // 0..127
    int c = threadIdx.x;     // 0..127
    float a0 = 0.f, a1 = 0.f, a2 = 0.f, a3 = 0.f;
#pragma unroll
    for (int j = 0; j < DIM; j += 4) {
        a0 += __ldg(&W[(j + 0) * DIM + r]) * __ldg(&W[(j + 0) * DIM + c]);
        a1 += __ldg(&W[(j + 1) * DIM + r]) * __ldg(&W[(j + 1) * DIM + c]);
        a2 += __ldg(&W[(j + 2) * DIM + r]) * __ldg(&W[(j + 2) * DIM + c]);
        a3 += __ldg(&W[(j + 3) * DIM + r]) * __ldg(&W[(j + 3) * DIM + c]);
    }
    g_M[r * DIM + c] = tf32r((a0 + a1) + (a2 + a3));
    if (r == 0) {
        float vv = 0.f;
#pragma unroll 8
        for (int j = 0; j < DIM; j++) vv += __ldg(&b[j]) * __ldg(&W[j * DIM + c]);
        g_v[c] = vv;
        if (c == 0) {
            float s = 0.f;
#pragma unroll 8
            for (int j = 0; j < DIM; j++) s += b[j] * b[j];
            g_c = s;
        }
    }
}

// ---------------- K_mark (main stream): mark needed nodes + zero agg rows ----
#define MARKBLOCKS (2 * BATCH / 32)
__global__ void k_mark(const int* __restrict__ ui, const int* __restrict__ ii) {
    int warp = threadIdx.x >> 5, lane = threadIdx.x & 31;
    int rowbase = blockIdx.x * 32 + warp * 4;
    int nodes[4];
#pragma unroll
    for (int q = 0; q < 4; q++) {
        int ref = rowbase + q;
        nodes[q] = (ref < BATCH) ? __ldg(&ui[ref])
                                 : (NUM_USERS + __ldg(&ii[ref - BATCH]));
    }
    const float4 z = make_float4(0.f, 0.f, 0.f, 0.f);
#pragma unroll
    for (int q = 0; q < 4; q++)
        ((float4*)(g_agg + (size_t)nodes[q] * DIM))[lane] = z;
    if (lane == 0) {
#pragma unroll
        for (int q = 0; q < 4; q++) g_mask[nodes[q]] = 1;
    }
}

// ---------------- K1: scan edges; 4 passing edges processed in parallel ------
// Warp = 4 groups of 8 lanes. Group g handles the (g+1)-th set ballot bit:
// 8 lanes x 4 float4 = one 512B row gather (coalesced) + 4 RED.128 per lane.
__global__ void k_edge(const int* __restrict__ src, const int* __restrict__ dst,
                       const float* __restrict__ uemb, const float* __restrict__ iemb) {
    int e = blockIdx.x * blockDim.x + threadIdx.x;
    int lane = threadIdx.x & 31;
    int grp = lane >> 3, sub = lane & 7;
    bool pass = false;
    int d = 0, s = 0;
    if (e < NUM_EDGES) {
        d = dst[e];
        pass = (g_mask[d] != 0);
        if (pass) s = src[e];
    }
    unsigned m = __ballot_sync(0xffffffffu, pass);
    while (m) {
        int cnt = __popc(m);
        int take = cnt < 4 ? cnt : 4;
        bool act = grp < take;
        int bit = act ? __fns(m, 0, grp + 1) : 0;
        int ds = __shfl_sync(0xffffffffu, d, bit);
        int ss = __shfl_sync(0xffffffffu, s, bit);
        if (act) {
            const float* sp = (ss < NUM_USERS)
                                ? (uemb + (size_t)ss * DIM)
                                : (iemb + (size_t)(ss - NUM_USERS) * DIM);
            const float4* sp4 = (const float4*)sp;
            float4 v0 = sp4[sub], v1 = sp4[sub + 8], v2 = sp4[sub + 16], v3 = sp4[sub + 24];
            float* a = g_agg + (size_t)ds * DIM;
            red4(a + sub * 4,       v0);
            red4(a + (sub + 8) * 4,  v1);
            red4(a + (sub + 16) * 4, v2);
            red4(a + (sub + 24) * 4, v3);
        }
#pragma unroll
        for (int q = 0; q < 4; q++)
            if (q < take) m &= m - 1;
    }
}

// ---------------- K2: mma.sync tf32 GEMM + fused bilinear epilogue -----------
// Pipelined cp.async staging:
//   group1 XI -> wait(2) -> round XI (M in flight)
//   group2 M  -> wait(1) -> MMA loop (XU in flight)
//   group3 XU -> wait(0) -> epilogue
#define MS_OFF   0
#define XI_OFF   (DIM * S * 4)
#define XU_OFF   (2 * DIM * S * 4)
#define VV_OFF   (3 * DIM * S * 4)
#define NDI_OFF  (VV_OFF + 512)
#define NDU_OFF  (NDI_OFF + 512)
#define PART_OFF (NDU_OFF + 512)
#define SMEM_K3  (PART_OFF + 2048)

__global__ void __launch_bounds__(512) k_pairs(
    const int* __restrict__ ui, const int* __restrict__ ii,
    float* __restrict__ out)
{
    extern __shared__ char sm[];
    uint32_t sbase = smem_u32(sm);
    float* Msm  = (float*)(sm + MS_OFF);    // Msm[j][k] (symmetric M)
    float* XIs  = (float*)(sm + XI_OFF);    // XIs[i][k], tf32-rounded
    float* XUs  = (float*)(sm + XU_OFF);    // XUs[i][k], fp32
    float* Vv   = (float*)(sm + VV_OFF);
    int*   Ndi  = (int*)(sm + NDI_OFF);
    int*   Ndu  = (int*)(sm + NDU_OFF);
    float* Part = (float*)(sm + PART_OFF);  // [128][4]

    int tid = threadIdx.x, warp = tid >> 5, lane = tid & 31;
    int base = blockIdx.x * BPB;
    int g = lane >> 2, t = lane & 3;

    // stage node indices + v (needed before the async gather)
    if (tid < 128) {
        Ndi[tid] = NUM_USERS + __ldg(&ii[base + tid]);
        Ndu[tid] = __ldg(&ui[base + tid]);
        Vv[tid]  = g_v[tid];
    }
    __syncthreads();

    // group 1: XI gather (4096 chunks, 8/thread; warp -> one 512B row/iter)
#pragma unroll
    for (int it = 0; it < 8; it++) {
        int idx = it * 512 + tid;
        int row = idx >> 5, f4 = idx & 31;
        cp16(sbase + XI_OFF + (row * S + 4 * f4) * 4,
             g_agg + (size_t)Ndi[row] * DIM + 4 * f4);
    }
    CP_COMMIT();
    // group 2: M restride (4096 chunks, 8/thread)
#pragma unroll
    for (int i = tid; i < DIM * DIM / 4; i += 512) {
        int r = i >> 5, c4 = i & 31;
        cp16(sbase + MS_OFF + (r * S + 4 * c4) * 4,
             (const char*)g_M + (r * DIM + 4 * c4) * 4);
    }
    CP_COMMIT();
    // group 3: XU gather
#pragma unroll
    for (int it = 0; it < 8; it++) {
        int idx = it * 512 + tid;
        int row = idx >> 5, f4 = idx & 31;
        cp16(sbase + XU_OFF + (row * S + 4 * f4) * 4,
             g_agg + (size_t)Ndu[row] * DIM + 4 * f4);
    }
    CP_COMMIT();

    // wait XI; round it to tf32 (RN) while M/XU are still in flight
    CP_WAIT(2);
    __syncthreads();
#pragma unroll
    for (int i = tid; i < DIM * DIM / 4; i += 512) {
        int row = i >> 5, f4 = i & 31;
        float4* p = (float4*)&XIs[row * S + 4 * f4];
        float4 v = *p;
        v.x = tf32r(v.x); v.y = tf32r(v.y); v.z = tf32r(v.z); v.w = tf32r(v.w);
        *p = v;
    }
    if (tid < 128) {            // restore mask invariant
        g_mask[Ndi[tid]] = 0;
        g_mask[Ndu[tid]] = 0;
    }
    // wait M; MMA can start (XU still in flight)
    CP_WAIT(1);
    __syncthreads();

    // warp tile: rows m0..m0+31, cols j0..j0+31
    int m0 = (warp & 3) * 32, j0 = (warp >> 2) * 32;
    float acc[2][4][4];
#pragma unroll
    for (int mi = 0; mi < 2; mi++)
#pragma unroll
        for (int ni = 0; ni < 4; ni++)
#pragma unroll
            for (int q = 0; q < 4; q++) acc[mi][ni][q] = 0.f;

#pragma unroll
    for (int k0 = 0; k0 < DIM; k0 += 8) {
        uint32_t a[2][4], b[4][2];
#pragma unroll
        for (int mi = 0; mi < 2; mi++) {
            const float* ap = XIs + (m0 + 16 * mi + g) * S + k0 + t;
            a[mi][0] = __float_as_uint(ap[0]);
            a[mi][1] = __float_as_uint(ap[8 * S]);
            a[mi][2] = __float_as_uint(ap[4]);
            a[mi][3] = __float_as_uint(ap[8 * S + 4]);
        }
#pragma unroll
        for (int ni = 0; ni < 4; ni++) {
            const float* bp = Msm + (j0 + 8 * ni + g) * S + k0 + t;
            b[ni][0] = __float_as_uint(bp[0]);
            b[ni][1] = __float_as_uint(bp[4]);
        }
#pragma unroll
        for (int mi = 0; mi < 2; mi++)
#pragma unroll
            for (int ni = 0; ni < 4; ni++)
                asm volatile(
                    "mma.sync.aligned.m16n8k8.row.col.f32.tf32.tf32.f32 "
                    "{%0,%1,%2,%3}, {%4,%5,%6,%7}, {%8,%9}, {%0,%1,%2,%3};"
                    : "+f"(acc[mi][ni][0]), "+f"(acc[mi][ni][1]),
                      "+f"(acc[mi][ni][2]), "+f"(acc[mi][ni][3])
                    : "r"(a[mi][0]), "r"(a[mi][1]), "r"(a[mi][2]), "r"(a[mi][3]),
                      "r"(b[ni][0]), "r"(b[ni][1]));
    }

    // wait XU before epilogue
    CP_WAIT(0);
    __syncthreads();

    // epilogue: p_row = sum_j in warp tile of [xu*(y+v) + v*xi]; reduce over t
    int nw = warp >> 2;
#pragma unroll
    for (int mi = 0; mi < 2; mi++) {
        int r_lo = m0 + 16 * mi + g;
        int r_hi = r_lo + 8;
        float plo = 0.f, phi = 0.f;
#pragma unroll
        for (int ni = 0; ni < 4; ni++) {
            int j = j0 + 8 * ni + 2 * t;
            float2 vl  = *(const float2*)&Vv[j];
            float2 xul = *(const float2*)&XUs[r_lo * S + j];
            float2 xuh = *(const float2*)&XUs[r_hi * S + j];
            float2 xil = *(const float2*)&XIs[r_lo * S + j];
            float2 xih = *(const float2*)&XIs[r_hi * S + j];
            plo += xul.x * (acc[mi][ni][0] + vl.x) + xul.y * (acc[mi][ni][1] + vl.y)
                 + vl.x * xil.x + vl.y * xil.y;
            phi += xuh.x * (acc[mi][ni][2] + vl.x) + xuh.y * (acc[mi][ni][3] + vl.y)
                 + vl.x * xih.x + vl.y * xih.y;
        }
        plo += __shfl_xor_sync(0xffffffffu, plo, 1);
        plo += __shfl_xor_sync(0xffffffffu, plo, 2);
        phi += __shfl_xor_sync(0xffffffffu, phi, 1);
        phi += __shfl_xor_sync(0xffffffffu, phi, 2);
        if (t == 0) {
            Part[r_lo * 4 + nw] = plo;
            Part[r_hi * 4 + nw] = phi;
        }
    }
    __syncthreads();

    if (tid < BPB) {
        float r = Part[tid * 4 + 0] + Part[tid * 4 + 1]
                + Part[tid * 4 + 2] + Part[tid * 4 + 3];
        out[base + tid] = r + g_c;
    }
}

// ---------------- launch (fork/join: k_m overlaps mark+edge) -----------------
extern "C" void kernel_launch(void* const* d_in, const int* in_sizes, int n_in,
                              void* d_out, int out_size) {
    const int*   ui   = (const int*)d_in[0];
    const int*   ii   = (const int*)d_in[1];
    const float* uemb = (const float*)d_in[2];
    const float* iemb = (const float*)d_in[3];
    const float* W    = (const float*)d_in[4];
    const float* b    = (const float*)d_in[5];
    const int*   ei   = (const int*)d_in[6];
    const int*   src  = ei;
    const int*   dst  = ei + NUM_EDGES;
    float*       out  = (float*)d_out;

    static cudaStream_t side = nullptr;
    static cudaEvent_t evFork = nullptr, evJoin = nullptr;
    if (!side) {
        cudaStreamCreateWithFlags(&side, cudaStreamNonBlocking);
        cudaEventCreateWithFlags(&evFork, cudaEventDisableTiming);
        cudaEventCreateWithFlags(&evJoin, cudaEventDisableTiming);
        cudaFuncSetAttribute(k_pairs, cudaFuncAttributeMaxDynamicSharedMemorySize, SMEM_K3);
    }

    // fork: side stream computes M/v/c while main stream does mark+edges
    cudaEventRecord(evFork, 0);
    cudaStreamWaitEvent(side, evFork, 0);
    k_m<<<DIM, DIM, 0, side>>>(W, b);
    cudaEventRecord(evJoin, side);

    k_mark<<<MARKBLOCKS, 256>>>(ui, ii);
    k_edge<<<(NUM_EDGES + 255) / 256, 256>>>(src, dst, uemb, iemb);

    cudaStreamWaitEvent(0, evJoin, 0);   // join before k_pairs (needs g_M/g_v/g_c)
    k_pairs<<<BATCH / BPB, 512, SMEM_K3>>>(ui, ii, out);
}